// round 5
// baseline (speedup 1.0000x reference)
#include <cuda_runtime.h>

#define TT   2048
#define NCTA 128
#define NTH  1024

typedef unsigned long long ull;

__device__ __forceinline__ ull pk2(float lo, float hi) {
    ull r; asm("mov.b64 %0, {%1,%2};" : "=l"(r) : "f"(lo), "f"(hi)); return r;
}
__device__ __forceinline__ float losum(ull v) {
    float lo, hi; asm("mov.b64 {%0,%1}, %2;" : "=f"(lo), "=f"(hi) : "l"(v));
    return lo + hi;
}
__device__ __forceinline__ ull ff2(ull a, ull b, ull c) {
    ull d; asm("fma.rn.f32x2 %0, %1, %2, %3;" : "=l"(d) : "l"(a), "l"(b), "l"(c));
    return d;
}
__device__ __forceinline__ float ex2f(float x){ float y; asm("ex2.approx.f32 %0, %1;" : "=f"(y) : "f"(x)); return y; }
__device__ __forceinline__ float rcpf(float x){ float y; asm("rcp.approx.f32 %0, %1;" : "=f"(y) : "f"(x)); return y; }
__device__ __forceinline__ float sigm(float x){ return rcpf(1.f + ex2f(-1.4426950408889634f * x)); }
__device__ __forceinline__ float tanh_(float x){ float e = ex2f(2.8853900817779268f * x); return 1.f - 2.f * rcpf(e + 1.f); }

// Row-thread GEMV: row r, 2 batches. Weights kb-major: w[kb*204]; v kb-major: v[kb*8].
template<int NB>
__device__ __forceinline__ void gemv2(const ulonglong2* __restrict__ w,
                                      const ulonglong2* __restrict__ va,
                                      const ulonglong2* __restrict__ vb,
                                      float bias, float* __restrict__ gout, bool gact)
{
    ull aAx = pk2(bias, 0.f), aAy = 0ULL;
    ull aBx = pk2(bias, 0.f), aBy = 0ULL;
#pragma unroll
    for (int kb = 0; kb < NB; ++kb) {
        const ulonglong2 wv = w[kb * 204];
        const ulonglong2 ha = va[kb * 8];
        const ulonglong2 hb = vb[kb * 8];
        aAx = ff2(wv.x, ha.x, aAx);
        aAy = ff2(wv.y, ha.y, aAy);
        aBx = ff2(wv.x, hb.x, aBx);
        aBy = ff2(wv.y, hb.y, aBy);
    }
    float sA = losum(aAx) + losum(aAy);
    float sB = losum(aBx) + losum(aBy);
    if (gact) { sA = tanh_(sA); sB = tanh_(sB); }
    else      { sA = sigm(sA);  sB = sigm(sB);  }
    *(float2*)gout = make_float2(sA, sB);
}

// smem layout (float offsets). Weights kb-major: idx = kb*816 + r*4 + w (col = kb*4+w).
// v arrays kb-major: idx = (c>>2)*32 + b*4 + (c&3).
#define OFF_W0 0            // 14*816
#define OFF_W1 11424        // 26*816
#define OFF_W2 32640        // 26*816
#define OFF_V0 53856        // 14*32
#define OFF_V1 54304        // 26*32
#define OFF_V2 55136        // 26*32
#define OFF_G  55968        // 204*8
#define OFF_WL 57600        // 104
#define OFF_BL 57704        // 2
#define SMEM_BYTES 230832

__device__ __forceinline__ int vidx(int c, int b) { return (c >> 2) * 32 + b * 4 + (c & 3); }

__global__ void __launch_bounds__(NTH, 1)
lstm_kernel(const float* __restrict__ inp,  const float* __restrict__ tim,
            const float* __restrict__ Wih0, const float* __restrict__ Whh0,
            const float* __restrict__ bih0, const float* __restrict__ bhh0,
            const float* __restrict__ Wih1, const float* __restrict__ Whh1,
            const float* __restrict__ bih1, const float* __restrict__ bhh1,
            const float* __restrict__ Wih2, const float* __restrict__ Whh2,
            const float* __restrict__ bih2, const float* __restrict__ bhh2,
            const float* __restrict__ Wlin, const float* __restrict__ blin,
            float* __restrict__ out)
{
    extern __shared__ float sm[];
    float* sW0 = sm + OFF_W0;  float* sW1 = sm + OFF_W1;  float* sW2 = sm + OFF_W2;
    float* sv0 = sm + OFF_V0;  float* sv1 = sm + OFF_V1;  float* sv2 = sm + OFF_V2;
    float* sg  = sm + OFF_G;   float* swl = sm + OFF_WL;  float* sbl = sm + OFF_BL;

    const int tid = threadIdx.x;
    const int gb0 = blockIdx.x * 8;

    // ---- weights into smem, kb-major ----
    for (int i = tid; i < 14 * 816; i += NTH) {       // W0 (56 cols: x0,x1,h(51),pad3)
        int kb = i / 816, rem = i - kb * 816, r = rem >> 2, w = rem & 3;
        int c = kb * 4 + w;
        float v = 0.f;
        if (c < 2)       v = Wih0[r * 2 + c];
        else if (c < 53) v = Whh0[r * 51 + (c - 2)];
        sW0[i] = v;
    }
    for (int i = tid; i < 26 * 816; i += NTH) {       // W1 (104 cols: h_in(51),pad,h(51),pad)
        int kb = i / 816, rem = i - kb * 816, r = rem >> 2, w = rem & 3;
        int c = kb * 4 + w;
        float v = 0.f;
        if (c < 51)                  v = Wih1[r * 51 + c];
        else if (c >= 52 && c < 103) v = Whh1[r * 51 + (c - 52)];
        sW1[i] = v;
    }
    for (int i = tid; i < 26 * 816; i += NTH) {       // W2
        int kb = i / 816, rem = i - kb * 816, r = rem >> 2, w = rem & 3;
        int c = kb * 4 + w;
        float v = 0.f;
        if (c < 51)                  v = Wih2[r * 51 + c];
        else if (c >= 52 && c < 103) v = Whh2[r * 51 + (c - 52)];
        sW2[i] = v;
    }
    for (int i = tid; i < 448; i += NTH) sv0[i] = 0.f;
    for (int i = tid; i < 832; i += NTH) { sv1[i] = 0.f; sv2[i] = 0.f; }
    for (int i = tid; i < 104; i += NTH) {
        int col = i / 52, kk = i - col * 52;
        swl[i] = (kk < 51) ? Wlin[col * 51 + kk] : 0.f;
    }
    if (tid < 2) sbl[tid] = blin[tid];
    __syncthreads();
    if (tid >= 960 && tid < 976) {                    // x(t=0): cols 0,1 of v0
        int idx = tid - 960, b = idx & 7, sel = idx >> 3;
        const float* src = sel ? tim : inp;
        sv0[b * 4 + sel] = src[(gb0 + b) * TT];
    }

    // roles
    const int r = tid >> 2;          // gemv row (tid < 816)
    const int q = tid & 3;           // batch pair
    const int b0 = 2 * q;
    float bias0 = 0.f, bias1 = 0.f, bias2 = 0.f;
    bool gact = false;
    if (tid < 816) {
        bias0 = bih0[r] + bhh0[r];
        bias1 = bih1[r] + bhh1[r];
        bias2 = bih2[r] + bhh2[r];
        gact  = (r >= 102 && r < 153);
    }
    const int uk = tid >> 3, ub = tid & 7;            // update role (tid < 408)
    float cc0 = 0.f, cc1 = 0.f, cc2 = 0.f;
    __syncthreads();

    const ulonglong2* w0p = (const ulonglong2*)sW0 + r;
    const ulonglong2* w1p = (const ulonglong2*)sW1 + r;
    const ulonglong2* w2p = (const ulonglong2*)sW2 + r;
    const ulonglong2* v0a = (const ulonglong2*)sv0 + b0;
    const ulonglong2* v0b = v0a + 1;
    const ulonglong2* v1a = (const ulonglong2*)sv1 + b0;
    const ulonglong2* v1b = v1a + 1;
    const ulonglong2* v2a = (const ulonglong2*)sv2 + b0;
    const ulonglong2* v2b = v2a + 1;
    float* gq = sg + r * 8 + b0;

    for (int t = 0; t < TT; ++t) {
        // ---- A0: L0 gates | head(t-1) | x(t+1) load ----
        float xin = 0.f; int xb = 0, xsel = 0;
        if (tid >= 960 && tid < 976 && (t + 1) < TT) {
            int idx = tid - 960; xb = idx & 7; xsel = idx >> 3;
            const float* src = xsel ? tim : inp;
            xin = src[(gb0 + xb) * TT + (t + 1)];
        }
        if (tid < 816) {
            gemv2<14>(w0p, v0a, v0b, bias0, gq, gact);
        } else if (tid >= 832 && tid < 848 && t > 0) {
            int idx = tid - 832, b = idx >> 1, col = idx & 1;
            float s = sbl[col];
#pragma unroll 1
            for (int kk = 0; kk < 51; ++kk)
                s += swl[col * 52 + kk] * sv2[vidx(52 + kk, b)];
            if (col) s = (s > 30.f) ? s : log1pf(__expf(s));
            out[((gb0 + b) * TT + (t - 1)) * 2 + col] = s;
        }
        __syncthreads();
        // ---- B0: L0 state update | x(t+1) store ----
        if (tid < 408) {
            float gi = sg[uk * 8 + ub];
            float gf = sg[(51 + uk) * 8 + ub];
            float gg = sg[(102 + uk) * 8 + ub];
            float go = sg[(153 + uk) * 8 + ub];
            cc0 = gf * cc0 + gi * gg;
            float h = go * tanh_(cc0);
            sv0[vidx(2 + uk, ub)] = h;
            sv1[vidx(uk, ub)]     = h;
        } else if (tid >= 960 && tid < 976 && (t + 1) < TT) {
            sv0[xb * 4 + xsel] = xin;
        }
        __syncthreads();
        // ---- A1 ----
        if (tid < 816) gemv2<26>(w1p, v1a, v1b, bias1, gq, gact);
        __syncthreads();
        // ---- B1 ----
        if (tid < 408) {
            float gi = sg[uk * 8 + ub];
            float gf = sg[(51 + uk) * 8 + ub];
            float gg = sg[(102 + uk) * 8 + ub];
            float go = sg[(153 + uk) * 8 + ub];
            cc1 = gf * cc1 + gi * gg;
            float h = go * tanh_(cc1);
            sv1[vidx(52 + uk, ub)] = h;
            sv2[vidx(uk, ub)]      = h;
        }
        __syncthreads();
        // ---- A2 ----
        if (tid < 816) gemv2<26>(w2p, v2a, v2b, bias2, gq, gact);
        __syncthreads();
        // ---- B2 ----
        if (tid < 408) {
            float gi = sg[uk * 8 + ub];
            float gf = sg[(51 + uk) * 8 + ub];
            float gg = sg[(102 + uk) * 8 + ub];
            float go = sg[(153 + uk) * 8 + ub];
            cc2 = gf * cc2 + gi * gg;
            float h = go * tanh_(cc2);
            sv2[vidx(52 + uk, ub)] = h;
        }
        __syncthreads();
    }
    // final head, t = TT-1
    if (tid >= 832 && tid < 848) {
        int idx = tid - 832, b = idx >> 1, col = idx & 1;
        float s = sbl[col];
#pragma unroll 1
        for (int kk = 0; kk < 51; ++kk)
            s += swl[col * 52 + kk] * sv2[vidx(52 + kk, b)];
        if (col) s = (s > 30.f) ? s : log1pf(__expf(s));
        out[((gb0 + b) * TT + (TT - 1)) * 2 + col] = s;
    }
}

extern "C" void kernel_launch(void* const* d_in, const int* in_sizes, int n_in,
                              void* d_out, int out_size)
{
    static bool attr_set = false;
    if (!attr_set) {
        cudaFuncSetAttribute(lstm_kernel,
                             cudaFuncAttributeMaxDynamicSharedMemorySize, SMEM_BYTES);
        attr_set = true;
    }
    lstm_kernel<<<NCTA, NTH, SMEM_BYTES>>>(
        (const float*)d_in[0],  (const float*)d_in[1],
        (const float*)d_in[2],  (const float*)d_in[3],
        (const float*)d_in[4],  (const float*)d_in[5],
        (const float*)d_in[6],  (const float*)d_in[7],
        (const float*)d_in[8],  (const float*)d_in[9],
        (const float*)d_in[10], (const float*)d_in[11],
        (const float*)d_in[12], (const float*)d_in[13],
        (const float*)d_in[14], (const float*)d_in[15],
        (float*)d_out);
}

// round 8
// speedup vs baseline: 1.7171x; 1.7171x over previous
#include <cuda_runtime.h>

#define TT   2048
#define NCTA 128
#define NTH  512

typedef unsigned long long ull;

__device__ __forceinline__ float losum(ull v) {
    float lo, hi; asm("mov.b64 {%0,%1}, %2;" : "=f"(lo), "=f"(hi) : "l"(v));
    return lo + hi;
}
__device__ __forceinline__ ull ff2(ull a, ull b, ull c) {
    ull d; asm("fma.rn.f32x2 %0, %1, %2, %3;" : "=l"(d) : "l"(a), "l"(b), "l"(c));
    return d;
}
__device__ __forceinline__ float ex2f(float x){ float y; asm("ex2.approx.f32 %0, %1;" : "=f"(y) : "f"(x)); return y; }
__device__ __forceinline__ float rcpf(float x){ float y; asm("rcp.approx.f32 %0, %1;" : "=f"(y) : "f"(x)); return y; }
__device__ __forceinline__ float sigm(float x){ return rcpf(1.f + ex2f(-1.4426950408889634f * x)); }
__device__ __forceinline__ float tanh_(float x){ float e = ex2f(2.8853900817779268f * x); return 1.f - 2.f * rcpf(e + 1.f); }

// Partial dot for 4 gate rows x 2 batches over J float4-chunks (this thread's K-half).
template<int J>
__device__ __forceinline__ void gates_partial(
    const ulonglong2* __restrict__ wt, int gstr,
    const ulonglong2* __restrict__ va, const ulonglong2* __restrict__ vb,
    float* __restrict__ partial)
{
    ull ax[4], ay[4], bx[4], by[4];
#pragma unroll
    for (int g = 0; g < 4; ++g) { ax[g] = 0ULL; ay[g] = 0ULL; bx[g] = 0ULL; by[g] = 0ULL; }
#pragma unroll
    for (int j = 0; j < J; ++j) {
        const ulonglong2 ha = va[j * 8];
        const ulonglong2 hb = vb[j * 8];
#pragma unroll
        for (int g = 0; g < 4; ++g) {
            const ulonglong2 wv = wt[g * gstr + j * 51];
            ax[g] = ff2(wv.x, ha.x, ax[g]);
            ay[g] = ff2(wv.y, ha.y, ay[g]);
            bx[g] = ff2(wv.x, hb.x, bx[g]);
            by[g] = ff2(wv.y, hb.y, by[g]);
        }
    }
#pragma unroll
    for (int g = 0; g < 4; ++g) {
        partial[g * 2 + 0] = losum(ax[g]) + losum(ay[g]);
        partial[g * 2 + 1] = losum(bx[g]) + losum(by[g]);
    }
}

// Exchange K-half partials with partner lane (s^1), finish own batch's gates, update c, return h.
__device__ __forceinline__ float lstm_update(const float* __restrict__ partial,
                                             const float* __restrict__ bias4,
                                             unsigned mask, int s, float& cc)
{
    float full[4];
#pragma unroll
    for (int g = 0; g < 4; ++g) {
        float prov = s ? partial[g * 2 + 0] : partial[g * 2 + 1];
        float recv = __shfl_xor_sync(mask, prov, 1);
        float mine = s ? partial[g * 2 + 1] : partial[g * 2 + 0];
        full[g] = mine + recv + bias4[g];
    }
    float gi = sigm(full[0]), gf = sigm(full[1]);
    float gg = tanh_(full[2]), go = sigm(full[3]);
    cc = gf * cc + gi * gg;
    return go * tanh_(cc);
}

// ---- smem layout (float4/ulonglong2 = 16B units) ----
#define OU2_W0 0
#define OU2_W1 2912
#define OU2_W2 8256
#define OU2_V0 13600
#define OU2_V1 13826
#define OU2_V2 14139
#define OU2_WL 14452
#define OU2_BL 14478
#define SMEM_BYTES (14479 * 16)

#define F_V0 (OU2_V0 * 4)
#define F_V1 (OU2_V1 * 4)
#define F_V2 (OU2_V2 * 4)
#define F_WL (OU2_WL * 4)
#define F_BL (OU2_BL * 4)

__global__ void __launch_bounds__(NTH, 1)
lstm_kernel(const float* __restrict__ inp,  const float* __restrict__ tim,
            const float* __restrict__ Wih0, const float* __restrict__ Whh0,
            const float* __restrict__ bih0, const float* __restrict__ bhh0,
            const float* __restrict__ Wih1, const float* __restrict__ Whh1,
            const float* __restrict__ bih1, const float* __restrict__ bhh1,
            const float* __restrict__ Wih2, const float* __restrict__ Whh2,
            const float* __restrict__ bih2, const float* __restrict__ bhh2,
            const float* __restrict__ Wlin, const float* __restrict__ blin,
            float* __restrict__ out)
{
    extern __shared__ float sm[];
    ulonglong2* smu2 = (ulonglong2*)sm;
    const int tid = threadIdx.x;
    const int gb0 = blockIdx.x * 8;

    // ---- W0: [g][s][j][k], s-stride 364 u2, g-stride 728 u2 ----
    for (int i = tid; i < 2912 * 4; i += NTH) {
        int f4 = i >> 2, e = i & 3;
        int gs = f4 / 364, rem = f4 - gs * 364;
        int j = rem / 51, kk = rem - j * 51;
        int g = gs >> 1, s = gs & 1;
        float v = 0.f;
        if (j < 7) {
            int c = s * 28 + j * 4 + e;
            int r = g * 51 + kk;
            if (c < 2)       v = Wih0[r * 2 + c];
            else if (c < 53) v = Whh0[r * 51 + (c - 2)];
        }
        sm[i] = v;
    }
    // ---- W1, W2: s-stride 668, g-stride 1336 ----
    for (int i = tid; i < 5344 * 4; i += NTH) {
        int f4 = i >> 2, e = i & 3;
        int gs = f4 / 668, rem = f4 - gs * 668;
        int j = rem / 51, kk = rem - j * 51;
        int g = gs >> 1, s = gs & 1;
        float v1 = 0.f, v2 = 0.f;
        if (j < 13) {
            int c = s * 52 + j * 4 + e;
            int r = g * 51 + kk;
            if (c < 51)                  { v1 = Wih1[r * 51 + c];        v2 = Wih2[r * 51 + c]; }
            else if (c >= 52 && c < 103) { v1 = Whh1[r * 51 + (c - 52)]; v2 = Whh2[r * 51 + (c - 52)]; }
        }
        sm[OU2_W1 * 4 + i] = v1;
        sm[OU2_W2 * 4 + i] = v2;
    }
    for (int i = tid; i < (OU2_WL - OU2_V0) * 4; i += NTH) sm[F_V0 + i] = 0.f;
    for (int i = tid; i < 104; i += NTH) {
        int col = i / 52, kk = i - col * 52;
        sm[F_WL + i] = (kk < 51) ? Wlin[col * 51 + kk] : 0.f;
    }
    if (tid < 2) sm[F_BL + tid] = blin[tid];
    __syncthreads();
    if (tid >= 448 && tid < 464) {     // x(t=0) into v0 buffer 0
        int idx = tid - 448, b = idx & 7, sel = idx >> 3;
        const float* src = sel ? tim : inp;
        sm[F_V0 + b * 4 + sel] = src[(gb0 + b) * TT];
    }

    // ---- roles ----
    const int s = tid & 1;
    const int q = (tid >> 1) & 3;
    const int k = tid >> 3;                 // 0..50 for tid<408
    const int b = 2 * q + s;
    const unsigned mask = (tid < 384) ? 0xFFFFFFFFu : 0x00FFFFFFu;

    float bias0[4], bias1[4], bias2[4];
    int h0off = 0, hinoff = 0, hownoff = 0;
    if (tid < 408) {
#pragma unroll
        for (int g = 0; g < 4; ++g) {
            int r = g * 51 + k;
            bias0[g] = bih0[r] + bhh0[r];
            bias1[g] = bih1[r] + bhh1[r];
            bias2[g] = bih2[r] + bhh2[r];
        }
        int c = k + 2;
        int f4o = (c < 28) ? ((c >> 2) * 8) : (57 + (((c - 28) >> 2) * 8));
        h0off   = (f4o + b) * 4 + (c & 3);
        hinoff  = ((k >> 2) * 8 + b) * 4 + (k & 3);
        hownoff = ((k >> 2) * 8 + b) * 4 + (k & 3);
    }
    const ulonglong2* w0t = smu2 + OU2_W0 + s * 364 + k;
    const ulonglong2* w1t = smu2 + OU2_W1 + s * 668 + k;
    const ulonglong2* w2t = smu2 + OU2_W2 + s * 668 + k;

    float cc0 = 0.f, cc1 = 0.f, cc2 = 0.f;
    __syncthreads();

    for (int t = 0; t < TT; ++t) {
        const int rp = t & 1, wp = 1 - rp;
        // ---- phase 0: L0 gemv+update | head(t-1) | x(t+1) load ----
        float xin = 0.f; int xb = 0, xsel = 0;
        if (tid < 408) {
            const ulonglong2* v0a = smu2 + OU2_V0 + rp * 113 + s * 57 + 2 * q;
            float partial[8];
            gates_partial<7>(w0t, 728, v0a, v0a + 1, partial);
            float h = lstm_update(partial, bias0, mask, s, cc0);
            sm[F_V0 + wp * 452 + h0off] = h;
            sm[F_V1 + hinoff] = h;
        } else if (tid >= 416 && tid < 432) {
            if (t > 0) {
                int idx = tid - 416, hb = idx >> 1, col = idx & 1;
                float acc = sm[F_BL + col];
                const float* h2 = sm + F_V2 + (105 + rp * 104) * 4;
#pragma unroll 1
                for (int kk = 0; kk < 51; ++kk)
                    acc += sm[F_WL + col * 52 + kk] * h2[((kk >> 2) * 8 + hb) * 4 + (kk & 3)];
                if (col) acc = (acc > 30.f) ? acc : log1pf(__expf(acc));
                out[((gb0 + hb) * TT + (t - 1)) * 2 + col] = acc;
            }
        } else if (tid >= 448 && tid < 464 && (t + 1) < TT) {
            int idx = tid - 448; xb = idx & 7; xsel = idx >> 3;
            const float* src = xsel ? tim : inp;
            xin = src[(gb0 + xb) * TT + (t + 1)];
        }
        __syncthreads();
        // ---- phase 1: L1 | x(t+1) store ----
        if (tid < 408) {
            const ulonglong2* v1a = s ? (smu2 + OU2_V1 + 105 + rp * 104 + 2 * q)
                                      : (smu2 + OU2_V1 + 2 * q);
            float partial[8];
            gates_partial<13>(w1t, 1336, v1a, v1a + 1, partial);
            float h = lstm_update(partial, bias1, mask, s, cc1);
            sm[F_V1 + (105 + wp * 104) * 4 + hownoff] = h;
            sm[F_V2 + hinoff] = h;
        } else if (tid >= 448 && tid < 464 && (t + 1) < TT) {
            sm[F_V0 + wp * 452 + xb * 4 + xsel] = xin;
        }
        __syncthreads();
        // ---- phase 2: L2 ----
        if (tid < 408) {
            const ulonglong2* v2a = s ? (smu2 + OU2_V2 + 105 + rp * 104 + 2 * q)
                                      : (smu2 + OU2_V2 + 2 * q);
            float partial[8];
            gates_partial<13>(w2t, 1336, v2a, v2a + 1, partial);
            float h = lstm_update(partial, bias2, mask, s, cc2);
            sm[F_V2 + (105 + wp * 104) * 4 + hownoff] = h;
        }
        __syncthreads();
    }
    // final head: t = TT-1
    if (tid >= 416 && tid < 432) {
        int idx = tid - 416, hb = idx >> 1, col = idx & 1;
        float acc = sm[F_BL + col];
        const float* h2 = sm + F_V2 + (105 + (TT & 1) * 104) * 4;
#pragma unroll 1
        for (int kk = 0; kk < 51; ++kk)
            acc += sm[F_WL + col * 52 + kk] * h2[((kk >> 2) * 8 + hb) * 4 + (kk & 3)];
        if (col) acc = (acc > 30.f) ? acc : log1pf(__expf(acc));
        out[((gb0 + hb) * TT + (TT - 1)) * 2 + col] = acc;
    }
}

extern "C" void kernel_launch(void* const* d_in, const int* in_sizes, int n_in,
                              void* d_out, int out_size)
{
    static bool attr_set = false;
    if (!attr_set) {
        cudaFuncSetAttribute(lstm_kernel,
                             cudaFuncAttributeMaxDynamicSharedMemorySize, SMEM_BYTES);
        attr_set = true;
    }
    lstm_kernel<<<NCTA, NTH, SMEM_BYTES>>>(
        (const float*)d_in[0],  (const float*)d_in[1],
        (const float*)d_in[2],  (const float*)d_in[3],
        (const float*)d_in[4],  (const float*)d_in[5],
        (const float*)d_in[6],  (const float*)d_in[7],
        (const float*)d_in[8],  (const float*)d_in[9],
        (const float*)d_in[10], (const float*)d_in[11],
        (const float*)d_in[12], (const float*)d_in[13],
        (const float*)d_in[14], (const float*)d_in[15],
        (float*)d_out);
}